// round 9
// baseline (speedup 1.0000x reference)
#include <cuda_runtime.h>

#define NN 10000     // nodes
#define KD 8         // out-degree
#define EE 80000     // edges
#define HDIM 512     // H*D

// Scratch (allocation-free rule: __device__ globals)
__device__ float g_nq[NN * HDIM];
__device__ float g_nk[NN * HDIM];
__device__ float g_nv[NN * HDIM];
__device__ float g_node[NN * HDIM];

// ---- packed f32x2 helpers (FFMA2 path: only reachable via PTX) ----
__device__ __forceinline__ unsigned long long pack2(float lo, float hi) {
    unsigned long long r;
    asm("mov.b64 %0, {%1, %2};" : "=l"(r) : "f"(lo), "f"(hi));
    return r;
}
__device__ __forceinline__ void ffma2(unsigned long long& d,
                                      unsigned long long a,
                                      unsigned long long b) {
    asm("fma.rn.f32x2 %0, %1, %2, %0;" : "+l"(d) : "l"(a), "l"(b));
}
__device__ __forceinline__ float2 unpack2(unsigned long long v) {
    float2 f;
    asm("mov.b64 {%0, %1}, %2;" : "=f"(f.x), "=f"(f.y) : "l"(v));
    return f;
}
__device__ __forceinline__ float f4c(const float4& v, int i) {
    return (i == 0) ? v.x : (i == 1) ? v.y : (i == 2) ? v.z : v.w;
}

// ---------------------------------------------------------------------------
// Kernel 1: fused QKV projection (unchanged).
// ---------------------------------------------------------------------------
__global__ __launch_bounds__(128) void proj_qkv_kernel(
    const float* __restrict__ X,
    const float* __restrict__ Wq, const float* __restrict__ bq,
    const float* __restrict__ Wk, const float* __restrict__ bk,
    const float* __restrict__ Wv, const float* __restrict__ bv)
{
    __shared__ float As[64][68];     // [row][k]
    __shared__ float Bs[64][132];    // [k][col]

    int bx  = blockIdx.x;
    int sel = bx >> 2;
    int c0  = (bx & 3) * 128;
    int r0  = blockIdx.y * 64;
    int t   = threadIdx.x;

    const float* W    = (sel == 0) ? Wq : (sel == 1) ? Wk : Wv;
    const float* bias = (sel == 0) ? bq : (sel == 1) ? bk : bv;
    float*       outp = (sel == 0) ? g_nq : (sel == 1) ? g_nk : g_nv;

    #pragma unroll
    for (int i = 0; i < 8; i++) {
        int idx = t + i * 128;
        int row = idx >> 4, k4 = idx & 15;
        float4 v = make_float4(0.f, 0.f, 0.f, 0.f);
        if (r0 + row < NN) v = *(const float4*)&X[(r0 + row) * 64 + k4 * 4];
        *(float4*)&As[row][k4 * 4] = v;
    }
    #pragma unroll
    for (int i = 0; i < 16; i++) {
        int idx = t + i * 128;
        int c = idx >> 4, k4 = idx & 15;
        float4 w = *(const float4*)&W[(c0 + c) * 64 + k4 * 4];
        Bs[k4*4+0][c] = w.x; Bs[k4*4+1][c] = w.y;
        Bs[k4*4+2][c] = w.z; Bs[k4*4+3][c] = w.w;
    }
    __syncthreads();

    int tx = t & 15, ty = t >> 4;
    unsigned long long acc[8][4] = {};

    #pragma unroll
    for (int k0 = 0; k0 < 64; k0 += 4) {
        float4 a4[8];
        #pragma unroll
        for (int i = 0; i < 8; i++) a4[i] = *(const float4*)&As[ty * 8 + i][k0];
        #pragma unroll
        for (int kk = 0; kk < 4; kk++) {
            unsigned long long b[4];
            #pragma unroll
            for (int p = 0; p < 4; p++)
                b[p] = *reinterpret_cast<const unsigned long long*>(&Bs[k0 + kk][tx * 2 + 32 * p]);
            #pragma unroll
            for (int i = 0; i < 8; i++) {
                float av = ((const float*)&a4[i])[kk];
                unsigned long long a = pack2(av, av);
                #pragma unroll
                for (int p = 0; p < 4; p++)
                    ffma2(acc[i][p], a, b[p]);
            }
        }
    }

    float2 bb[4];
    #pragma unroll
    for (int p = 0; p < 4; p++) {
        int c = c0 + tx * 2 + 32 * p;
        bb[p] = make_float2(bias[c], bias[c + 1]);
    }
    #pragma unroll
    for (int i = 0; i < 8; i++) {
        int row = r0 + ty * 8 + i;
        if (row < NN) {
            #pragma unroll
            for (int p = 0; p < 4; p++) {
                int c = c0 + tx * 2 + 32 * p;
                float2 r = unpack2(acc[i][p]);
                *(float2*)&outp[(long)row * HDIM + c] =
                    make_float2(r.x + bb[p].x, r.y + bb[p].y);
            }
        }
    }
}

// ---------------------------------------------------------------------------
// Kernel 2: warp-per-node fused pipeline. smem diet: ev lives in registers,
// ef/sqk stored transposed for edge-paired f32x2 phase 2. 7 blocks/SM target.
// ---------------------------------------------------------------------------
__global__ __launch_bounds__(128, 7) void node_edge_kernel(
    const float* __restrict__ edge_features,
    const int*   __restrict__ edge_index,
    const float* __restrict__ Weq, const float* __restrict__ beq,
    const float* __restrict__ Wev, const float* __restrict__ bev,
    const float* __restrict__ Wek, const float* __restrict__ bek,
    const float* __restrict__ Wel, const float* __restrict__ bel,
    const float* __restrict__ Wele, const float* __restrict__ bele,
    float* __restrict__ out_edge)
{
    __shared__ __align__(16) float s_Wel[8][68];     // [h][c]
    __shared__ float s_Wele[16][9];                  // [de][h]
    __shared__ __align__(16) float s_eq[4][8][68];   // eq, reused as eout
    __shared__ __align__(16) float s_ek[4][8][68];
    __shared__ __align__(8)  float s_efT[4][16][10]; // [c][j]
    __shared__ __align__(8)  float s_sqkT[4][8][10]; // [h][j]
    __shared__ __align__(16) float s_att[4][8][4][8];
    __shared__ float s_ee[4][8][9];
    __shared__ float s_attn[4][8][9];

    int t    = threadIdx.x;
    int nd   = t >> 5;
    int lane = t & 31;
    int n    = blockIdx.x * 4 + nd;

    // ---- stage small weights (block-coop) ----
    for (int i = t; i < 512; i += 128) s_Wel[i >> 6][i & 63] = Wel[i];
    s_Wele[t >> 3][t & 7] = Wele[t];   // t < 128
    __syncthreads();

    // ---- e1 via warp shuffle ----
    int ej = (lane < 8) ? edge_index[EE + n * 8 + lane] : 0;
    int e1r[8];
    #pragma unroll
    for (int j = 0; j < 8; j++) e1r[j] = __shfl_sync(0xffffffffu, ej, j);

    // ---- edge features, stored transposed [c][j] ----
    {
        float4 f = ((const float4*)(edge_features + (long)n * 128))[lane];
        int j = lane >> 2, c4 = lane & 3;
        s_efT[nd][c4 * 4 + 0][j] = f.x;
        s_efT[nd][c4 * 4 + 1][j] = f.y;
        s_efT[nd][c4 * 4 + 2][j] = f.z;
        s_efT[nd][c4 * 4 + 3][j] = f.w;
    }

    // ---- phase 1: sqk (head-aligned, 4 lanes per head, 2 shuffles) ----
    {
        int hh = lane >> 2, mm = lane & 3;
        const float4* qp = (const float4*)(g_nq + (long)n * 512);
        float4 q4[4];
        #pragma unroll
        for (int i = 0; i < 4; i++) q4[i] = qp[hh * 16 + mm + 4 * i];
        #pragma unroll
        for (int j = 0; j < 8; j++) {
            const float4* kp = (const float4*)(g_nk + (long)e1r[j] * 512);
            float s = 0.f;
            #pragma unroll
            for (int i = 0; i < 4; i++) {
                float4 kv = __ldg(&kp[hh * 16 + mm + 4 * i]);
                s += q4[i].x * kv.x + q4[i].y * kv.y + q4[i].z * kv.z + q4[i].w * kv.w;
            }
            s += __shfl_xor_sync(0xffffffffu, s, 1);
            s += __shfl_xor_sync(0xffffffffu, s, 2);
            if (mm == 0) s_sqkT[nd][hh][j] = s * 0.125f;
        }
    }
    __syncwarp();

    // ---- phase 2: eq/ek (to smem), ev (kept in registers) ----
    int uA = lane, uB = lane + 32;
    unsigned long long av[2][4];     // ev accumulators: [col][edge-pair]
    {
        // -- eq --
        unsigned long long aq[2][4];
        {
            unsigned long long bA = pack2(__ldg(&beq[uA]), __ldg(&beq[uA]));
            unsigned long long bB = pack2(__ldg(&beq[uB]), __ldg(&beq[uB]));
            #pragma unroll
            for (int jp = 0; jp < 4; jp++) { aq[0][jp] = bA; aq[1][jp] = bB; }
        }
        #pragma unroll
        for (int c4 = 0; c4 < 4; c4++) {
            float4 wA = __ldg((const float4*)Weq + uA * 4 + c4);
            float4 wB = __ldg((const float4*)Weq + uB * 4 + c4);
            #pragma unroll
            for (int cc = 0; cc < 4; cc++) {
                int c = c4 * 4 + cc;
                unsigned long long w2A = pack2(f4c(wA, cc), f4c(wA, cc));
                unsigned long long w2B = pack2(f4c(wB, cc), f4c(wB, cc));
                #pragma unroll
                for (int jp = 0; jp < 4; jp++) {
                    unsigned long long e2 =
                        *reinterpret_cast<const unsigned long long*>(&s_efT[nd][c][2 * jp]);
                    ffma2(aq[0][jp], e2, w2A);
                    ffma2(aq[1][jp], e2, w2B);
                }
            }
        }
        #pragma unroll
        for (int jp = 0; jp < 4; jp++) {
            float2 vA = unpack2(aq[0][jp]);
            float2 vB = unpack2(aq[1][jp]);
            s_eq[nd][2*jp+0][uA] = vA.x; s_eq[nd][2*jp+1][uA] = vA.y;
            s_eq[nd][2*jp+0][uB] = vB.x; s_eq[nd][2*jp+1][uB] = vB.y;
        }
        // -- ek --
        unsigned long long ak[2][4];
        {
            unsigned long long bA = pack2(__ldg(&bek[uA]), __ldg(&bek[uA]));
            unsigned long long bB = pack2(__ldg(&bek[uB]), __ldg(&bek[uB]));
            #pragma unroll
            for (int jp = 0; jp < 4; jp++) { ak[0][jp] = bA; ak[1][jp] = bB; }
        }
        #pragma unroll
        for (int c2 = 0; c2 < 2; c2++) {
            float4 wA = __ldg((const float4*)Wek + uA * 2 + c2);
            float4 wB = __ldg((const float4*)Wek + uB * 2 + c2);
            #pragma unroll
            for (int cc = 0; cc < 4; cc++) {
                int c = c2 * 4 + cc;
                unsigned long long w2A = pack2(f4c(wA, cc), f4c(wA, cc));
                unsigned long long w2B = pack2(f4c(wB, cc), f4c(wB, cc));
                #pragma unroll
                for (int jp = 0; jp < 4; jp++) {
                    unsigned long long e2 =
                        *reinterpret_cast<const unsigned long long*>(&s_sqkT[nd][c][2 * jp]);
                    ffma2(ak[0][jp], e2, w2A);
                    ffma2(ak[1][jp], e2, w2B);
                }
            }
        }
        #pragma unroll
        for (int jp = 0; jp < 4; jp++) {
            float2 vA = unpack2(ak[0][jp]);
            float2 vB = unpack2(ak[1][jp]);
            s_ek[nd][2*jp+0][uA] = vA.x; s_ek[nd][2*jp+1][uA] = vA.y;
            s_ek[nd][2*jp+0][uB] = vB.x; s_ek[nd][2*jp+1][uB] = vB.y;
        }
        // -- ev (registers only) --
        {
            unsigned long long bA = pack2(__ldg(&bev[uA]), __ldg(&bev[uA]));
            unsigned long long bB = pack2(__ldg(&bev[uB]), __ldg(&bev[uB]));
            #pragma unroll
            for (int jp = 0; jp < 4; jp++) { av[0][jp] = bA; av[1][jp] = bB; }
        }
        #pragma unroll
        for (int c4 = 0; c4 < 4; c4++) {
            float4 wA = __ldg((const float4*)Wev + uA * 4 + c4);
            float4 wB = __ldg((const float4*)Wev + uB * 4 + c4);
            #pragma unroll
            for (int cc = 0; cc < 4; cc++) {
                int c = c4 * 4 + cc;
                unsigned long long w2A = pack2(f4c(wA, cc), f4c(wA, cc));
                unsigned long long w2B = pack2(f4c(wB, cc), f4c(wB, cc));
                #pragma unroll
                for (int jp = 0; jp < 4; jp++) {
                    unsigned long long e2 =
                        *reinterpret_cast<const unsigned long long*>(&s_efT[nd][c][2 * jp]);
                    ffma2(av[0][jp], e2, w2A);
                    ffma2(av[1][jp], e2, w2B);
                }
            }
        }
    }
    __syncwarp();

    // ---- phase 3: edge-edge attention. 2 (q,k) pairs per lane ----
    #pragma unroll
    for (int rep = 0; rep < 2; rep++) {
        int p = lane + 32 * rep;
        int q = p >> 3, k = p & 7;
        const float4* eqp = (const float4*)&s_eq[nd][q][0];
        const float4* ekp = (const float4*)&s_ek[nd][k][0];
        #pragma unroll
        for (int eh = 0; eh < 4; eh++) {
            float s = 0.f;
            #pragma unroll
            for (int c = 0; c < 4; c++) {
                float4 a = eqp[eh * 4 + c];
                float4 b = ekp[eh * 4 + c];
                s += a.x * b.x + a.y * b.y + a.z * b.z + a.w * b.w;
            }
            s *= 0.25f;
            float mx = s;
            mx = fmaxf(mx, __shfl_xor_sync(0xffffffffu, mx, 1));
            mx = fmaxf(mx, __shfl_xor_sync(0xffffffffu, mx, 2));
            mx = fmaxf(mx, __shfl_xor_sync(0xffffffffu, mx, 4));
            float ex = __expf(s - mx);
            float sm = ex;
            sm += __shfl_xor_sync(0xffffffffu, sm, 1);
            sm += __shfl_xor_sync(0xffffffffu, sm, 2);
            sm += __shfl_xor_sync(0xffffffffu, sm, 4);
            s_att[nd][q][eh][k] = __fdividef(ex, sm + 1e-16f);
        }
    }
    __syncwarp();

    // ---- phase 4: eout[q][u] = sum_k att[q][eh(u)][k] * ev[k][u] ----
    #pragma unroll
    for (int rep = 0; rep < 2; rep++) {
        int u = lane + 32 * rep;
        int eh = u >> 4;
        float evr[8];
        #pragma unroll
        for (int jp = 0; jp < 4; jp++) {
            float2 p2 = unpack2(av[rep][jp]);
            evr[2*jp] = p2.x; evr[2*jp+1] = p2.y;
        }
        #pragma unroll
        for (int q = 0; q < 8; q++) {
            float4 a0 = *(const float4*)&s_att[nd][q][eh][0];
            float4 a1 = *(const float4*)&s_att[nd][q][eh][4];
            float acc = 0.f;
            acc = fmaf(a0.x, evr[0], acc); acc = fmaf(a0.y, evr[1], acc);
            acc = fmaf(a0.z, evr[2], acc); acc = fmaf(a0.w, evr[3], acc);
            acc = fmaf(a1.x, evr[4], acc); acc = fmaf(a1.y, evr[5], acc);
            acc = fmaf(a1.z, evr[6], acc); acc = fmaf(a1.w, evr[7], acc);
            s_eq[nd][q][u] = acc;          // eq reused as eout
        }
    }
    __syncwarp();

    // ---- phase 5: edge_emb[q][h] = eout[q] . Wel[h] + bel[h] ----
    #pragma unroll
    for (int rep = 0; rep < 2; rep++) {
        int p = lane + 32 * rep;
        int q = p >> 3, h = p & 7;
        float acc = __ldg(&bel[h]);
        const float4* ep = (const float4*)&s_eq[nd][q][0];
        const float4* wp = (const float4*)&s_Wel[h][0];
        #pragma unroll
        for (int c = 0; c < 16; c++) {
            float4 e = ep[c], w = wp[c];
            acc += e.x * w.x + e.y * w.y + e.z * w.z + e.w * w.w;
        }
        s_ee[nd][q][h] = acc;
    }
    __syncwarp();

    // ---- phase 6a: node softmax (lanes 0-7) ----
    if (lane < 8) {
        int h = lane;
        float l[8], mx = -1e30f;
        #pragma unroll
        for (int j = 0; j < 8; j++) {
            l[j] = s_ee[nd][j][h] + s_sqkT[nd][h][j];
            mx = fmaxf(mx, l[j]);
        }
        float sm = 0.f;
        #pragma unroll
        for (int j = 0; j < 8; j++) { l[j] = __expf(l[j] - mx); sm += l[j]; }
        float inv = __fdividef(1.f, sm + 1e-16f);
        #pragma unroll
        for (int j = 0; j < 8; j++) s_attn[nd][j][h] = l[j] * inv;
    }
    // ---- phase 6b: edge_embeddings output ----
    #pragma unroll
    for (int rep = 0; rep < 2; rep++) {
        int p = lane + 32 * rep;
        int q = p >> 3, d2 = (p & 7) * 2;
        float a0 = __ldg(&bele[d2]), a1 = __ldg(&bele[d2 + 1]);
        #pragma unroll
        for (int h = 0; h < 8; h++) {
            float e = s_ee[nd][q][h];
            a0 = fmaf(e, s_Wele[d2][h], a0);
            a1 = fmaf(e, s_Wele[d2 + 1][h], a1);
        }
        *(float2*)&out_edge[(n * 8 + q) * 16 + d2] = make_float2(a0, a1);
    }
    __syncwarp();

    // ---- phase 7: node aggregation into g_node ----
    #pragma unroll
    for (int i = 0; i < 4; i++) {
        int c4 = lane + 32 * i;            // float4 column index
        int h  = c4 >> 4;
        float4 acc = make_float4(0.f, 0.f, 0.f, 0.f);
        #pragma unroll
        for (int j = 0; j < 8; j++) {
            float w = s_attn[nd][j][h];
            float4 v = __ldg((const float4*)(g_nv + (long)e1r[j] * 512) + c4);
            acc.x = fmaf(w, v.x, acc.x); acc.y = fmaf(w, v.y, acc.y);
            acc.z = fmaf(w, v.z, acc.z); acc.w = fmaf(w, v.w, acc.w);
        }
        ((float4*)(g_node + (long)n * 512))[c4] = acc;
    }
}

// ---------------------------------------------------------------------------
// Kernel 3: node_embeddings = g_node[10000,512] @ Wlin^T[512,64] + blin
// ---------------------------------------------------------------------------
__global__ __launch_bounds__(256) void out_gemm_kernel(
    const float* __restrict__ Wlin, const float* __restrict__ blin,
    float* __restrict__ out)
{
    __shared__ float As[64][68];
    __shared__ float Ws[64][66];
    int r0 = blockIdx.x * 64;
    int t  = threadIdx.x;
    int tx = t & 15, ty = t >> 4;
    unsigned long long acc[4][2] = {};

    for (int k0g = 0; k0g < 512; k0g += 64) {
        __syncthreads();
        #pragma unroll
        for (int i = 0; i < 4; i++) {
            int idx = t + i * 256;
            int row = idx >> 4, k4 = idx & 15;
            float4 v = make_float4(0.f, 0.f, 0.f, 0.f);
            if (r0 + row < NN) v = *(const float4*)&g_node[(long)(r0 + row) * 512 + k0g + k4 * 4];
            *(float4*)&As[row][k4 * 4] = v;
            float4 w = *(const float4*)&Wlin[(long)row * 512 + k0g + k4 * 4];
            Ws[k4*4+0][row] = w.x; Ws[k4*4+1][row] = w.y;
            Ws[k4*4+2][row] = w.z; Ws[k4*4+3][row] = w.w;
        }
        __syncthreads();
        #pragma unroll
        for (int k0 = 0; k0 < 64; k0 += 4) {
            float4 a4[4];
            #pragma unroll
            for (int i = 0; i < 4; i++) a4[i] = *(const float4*)&As[ty * 4 + i][k0];
            #pragma unroll
            for (int kk = 0; kk < 4; kk++) {
                unsigned long long b[2];
                #pragma unroll
                for (int p = 0; p < 2; p++)
                    b[p] = *reinterpret_cast<const unsigned long long*>(&Ws[k0 + kk][tx * 2 + 32 * p]);
                #pragma unroll
                for (int i = 0; i < 4; i++) {
                    float av = ((const float*)&a4[i])[kk];
                    unsigned long long a = pack2(av, av);
                    #pragma unroll
                    for (int p = 0; p < 2; p++)
                        ffma2(acc[i][p], a, b[p]);
                }
            }
        }
    }

    #pragma unroll
    for (int i = 0; i < 4; i++) {
        int row = r0 + ty * 4 + i;
        if (row < NN) {
            #pragma unroll
            for (int p = 0; p < 2; p++) {
                int d = tx * 2 + 32 * p;
                float2 r = unpack2(acc[i][p]);
                *(float2*)&out[(long)row * 64 + d] =
                    make_float2(r.x + blin[d], r.y + blin[d + 1]);
            }
        }
    }
}

// ---------------------------------------------------------------------------
extern "C" void kernel_launch(void* const* d_in, const int* in_sizes, int n_in,
                              void* d_out, int out_size)
{
    const float* x    = (const float*)d_in[0];
    const float* ef   = (const float*)d_in[1];
    const float* Wq   = (const float*)d_in[2];
    const float* bq   = (const float*)d_in[3];
    const float* Wk   = (const float*)d_in[4];
    const float* bk   = (const float*)d_in[5];
    const float* Wv   = (const float*)d_in[6];
    const float* bv   = (const float*)d_in[7];
    const float* Wlin = (const float*)d_in[8];
    const float* blin = (const float*)d_in[9];
    const float* Weq  = (const float*)d_in[10];
    const float* beq  = (const float*)d_in[11];
    const float* Wev  = (const float*)d_in[12];
    const float* bev  = (const float*)d_in[13];
    const float* Wek  = (const float*)d_in[14];
    const float* bek  = (const float*)d_in[15];
    const float* Wel  = (const float*)d_in[16];
    const float* bel  = (const float*)d_in[17];
    const float* Wele = (const float*)d_in[18];
    const float* bele = (const float*)d_in[19];
    const int*   eidx = (const int*)d_in[20];
    float* out = (float*)d_out;

    proj_qkv_kernel<<<dim3(12, 157), 128>>>(x, Wq, bq, Wk, bk, Wv, bv);
    node_edge_kernel<<<NN / 4, 128>>>(ef, eidx, Weq, beq, Wev, bev, Wek, bek,
                                      Wel, bel, Wele, bele, out + NN * 64);
    out_gemm_kernel<<<157, 256>>>(Wlin, blin, out);
}

// round 10
// speedup vs baseline: 1.1879x; 1.1879x over previous
#include <cuda_runtime.h>

#define NN 10000     // nodes
#define KD 8         // out-degree
#define EE 80000     // edges
#define HDIM 512     // H*D

// Scratch (allocation-free rule: __device__ globals)
__device__ float g_nq[NN * HDIM];
__device__ float g_nk[NN * HDIM];
__device__ float g_nv[NN * HDIM];
__device__ float g_node[NN * HDIM];

// ---- packed f32x2 helpers (FFMA2 path: only reachable via PTX) ----
__device__ __forceinline__ unsigned long long pack2(float lo, float hi) {
    unsigned long long r;
    asm("mov.b64 %0, {%1, %2};" : "=l"(r) : "f"(lo), "f"(hi));
    return r;
}
__device__ __forceinline__ void ffma2(unsigned long long& d,
                                      unsigned long long a,
                                      unsigned long long b) {
    asm("fma.rn.f32x2 %0, %1, %2, %0;" : "+l"(d) : "l"(a), "l"(b));
}
__device__ __forceinline__ float2 unpack2(unsigned long long v) {
    float2 f;
    asm("mov.b64 {%0, %1}, %2;" : "=f"(f.x), "=f"(f.y) : "l"(v));
    return f;
}
__device__ __forceinline__ float f4c(const float4& v, int i) {
    return (i == 0) ? v.x : (i == 1) ? v.y : (i == 2) ? v.z : v.w;
}

// ---------------------------------------------------------------------------
// Kernel 1: fused QKV projection. 64x128 tile, 8x8 microtile with 8
// CONTIGUOUS columns per thread: B operand = 2x LDS.128, epilogue 2x STG.128.
// ---------------------------------------------------------------------------
__global__ __launch_bounds__(128) void proj_qkv_kernel(
    const float* __restrict__ X,
    const float* __restrict__ Wq, const float* __restrict__ bq,
    const float* __restrict__ Wk, const float* __restrict__ bk,
    const float* __restrict__ Wv, const float* __restrict__ bv)
{
    __shared__ float As[64][68];                      // [row][k]
    __shared__ __align__(16) float Bs[64][132];       // [k][col]

    int bx  = blockIdx.x;
    int sel = bx >> 2;
    int c0  = (bx & 3) * 128;
    int r0  = blockIdx.y * 64;
    int t   = threadIdx.x;

    const float* W    = (sel == 0) ? Wq : (sel == 1) ? Wk : Wv;
    const float* bias = (sel == 0) ? bq : (sel == 1) ? bk : bv;
    float*       outp = (sel == 0) ? g_nq : (sel == 1) ? g_nk : g_nv;

    #pragma unroll
    for (int i = 0; i < 8; i++) {
        int idx = t + i * 128;
        int row = idx >> 4, k4 = idx & 15;
        float4 v = make_float4(0.f, 0.f, 0.f, 0.f);
        if (r0 + row < NN) v = *(const float4*)&X[(r0 + row) * 64 + k4 * 4];
        *(float4*)&As[row][k4 * 4] = v;
    }
    #pragma unroll
    for (int i = 0; i < 16; i++) {
        int idx = t + i * 128;
        int c = idx >> 4, k4 = idx & 15;
        float4 w = *(const float4*)&W[(c0 + c) * 64 + k4 * 4];
        Bs[k4*4+0][c] = w.x; Bs[k4*4+1][c] = w.y;
        Bs[k4*4+2][c] = w.z; Bs[k4*4+3][c] = w.w;
    }
    __syncthreads();

    int tx = t & 15, ty = t >> 4;
    unsigned long long acc[8][4] = {};

    #pragma unroll
    for (int k0 = 0; k0 < 64; k0 += 4) {
        float4 a4[8];
        #pragma unroll
        for (int i = 0; i < 8; i++) a4[i] = *(const float4*)&As[ty * 8 + i][k0];
        #pragma unroll
        for (int kk = 0; kk < 4; kk++) {
            ulonglong2 q0 = *(const ulonglong2*)&Bs[k0 + kk][tx * 8];
            ulonglong2 q1 = *(const ulonglong2*)&Bs[k0 + kk][tx * 8 + 4];
            unsigned long long b[4] = {q0.x, q0.y, q1.x, q1.y};
            #pragma unroll
            for (int i = 0; i < 8; i++) {
                float av = ((const float*)&a4[i])[kk];
                unsigned long long a = pack2(av, av);
                #pragma unroll
                for (int p = 0; p < 4; p++)
                    ffma2(acc[i][p], a, b[p]);
            }
        }
    }

    float4 bb0 = *(const float4*)&bias[c0 + tx * 8];
    float4 bb1 = *(const float4*)&bias[c0 + tx * 8 + 4];
    #pragma unroll
    for (int i = 0; i < 8; i++) {
        int row = r0 + ty * 8 + i;
        if (row < NN) {
            float2 r0p = unpack2(acc[i][0]);
            float2 r1p = unpack2(acc[i][1]);
            float2 r2p = unpack2(acc[i][2]);
            float2 r3p = unpack2(acc[i][3]);
            float4 o0 = make_float4(r0p.x + bb0.x, r0p.y + bb0.y,
                                    r1p.x + bb0.z, r1p.y + bb0.w);
            float4 o1 = make_float4(r2p.x + bb1.x, r2p.y + bb1.y,
                                    r3p.x + bb1.z, r3p.y + bb1.w);
            *(float4*)&outp[(long)row * HDIM + c0 + tx * 8]     = o0;
            *(float4*)&outp[(long)row * HDIM + c0 + tx * 8 + 4] = o1;
        }
    }
}

// ---------------------------------------------------------------------------
// Kernel 2: warp-per-node fused pipeline (R8 structure, best known) with
// fast-math exp/div only.
// ---------------------------------------------------------------------------
__global__ __launch_bounds__(128) void node_edge_kernel(
    const float* __restrict__ edge_features,
    const int*   __restrict__ edge_index,
    const float* __restrict__ Weq, const float* __restrict__ beq,
    const float* __restrict__ Wev, const float* __restrict__ bev,
    const float* __restrict__ Wek, const float* __restrict__ bek,
    const float* __restrict__ Wel, const float* __restrict__ bel,
    const float* __restrict__ Wele, const float* __restrict__ bele,
    float* __restrict__ out_edge)
{
    __shared__ __align__(16) float s_Wel[8][68];  // [h][c]
    __shared__ float s_Wele[16][9];               // [de][h]
    // per-node (warp-private) state
    __shared__ __align__(16) float s_ef[4][8][16];
    __shared__ __align__(16) float s_eq[4][8][68];   // eq, reused as eout
    __shared__ __align__(16) float s_ev[4][8][68];
    __shared__ __align__(16) float s_ek[4][8][68];
    __shared__ __align__(16) float s_att[4][8][4][8];
    __shared__ float s_sqk[4][8][8];
    __shared__ float s_ee[4][8][8];
    __shared__ float s_attn[4][8][8];

    int t    = threadIdx.x;
    int nd   = t >> 5;
    int lane = t & 31;
    int n    = blockIdx.x * 4 + nd;

    // ---- stage small weights (block-coop) ----
    for (int i = t; i < 512; i += 128) s_Wel[i >> 6][i & 63] = Wel[i];
    s_Wele[t >> 3][t & 7] = Wele[t];   // t < 128
    __syncthreads();

    // ---- e1 via warp shuffle ----
    int ej = (lane < 8) ? edge_index[EE + n * 8 + lane] : 0;
    int e1r[8];
    #pragma unroll
    for (int j = 0; j < 8; j++) e1r[j] = __shfl_sync(0xffffffffu, ej, j);

    // ---- edge features (128 floats, one float4 per lane) ----
    ((float4*)&s_ef[nd][0][0])[lane] =
        ((const float4*)(edge_features + (long)n * 128))[lane];

    // ---- phase 1: sqk[j][h] head-aligned; 4 lanes per head, 2 shuffles ----
    {
        int hh = lane >> 2, mm = lane & 3;
        const float4* qp = (const float4*)(g_nq + (long)n * 512);
        float4 q4[4];
        #pragma unroll
        for (int i = 0; i < 4; i++) q4[i] = qp[hh * 16 + mm + 4 * i];
        #pragma unroll
        for (int j = 0; j < 8; j++) {
            const float4* kp = (const float4*)(g_nk + (long)e1r[j] * 512);
            float s = 0.f;
            #pragma unroll
            for (int i = 0; i < 4; i++) {
                float4 kv = __ldg(&kp[hh * 16 + mm + 4 * i]);
                s += q4[i].x * kv.x + q4[i].y * kv.y + q4[i].z * kv.z + q4[i].w * kv.w;
            }
            s += __shfl_xor_sync(0xffffffffu, s, 1);
            s += __shfl_xor_sync(0xffffffffu, s, 2);
            if (mm == 0) s_sqk[nd][j][hh] = s * 0.125f;
        }
    }
    __syncwarp();

    // ---- phase 2: eq/ev/ek. lane owns cols uA=lane, uB=lane+32 (f32x2) ----
    {
        int uA = lane, uB = lane + 32;
        // eq/ev
        unsigned long long aq[8], av[8];
        {
            unsigned long long bq2 = pack2(__ldg(&beq[uA]), __ldg(&beq[uB]));
            unsigned long long bv2 = pack2(__ldg(&bev[uA]), __ldg(&bev[uB]));
            #pragma unroll
            for (int j = 0; j < 8; j++) { aq[j] = bq2; av[j] = bv2; }
        }
        #pragma unroll
        for (int c4 = 0; c4 < 4; c4++) {
            float4 wqA = __ldg((const float4*)Weq + uA * 4 + c4);
            float4 wqB = __ldg((const float4*)Weq + uB * 4 + c4);
            float4 wvA = __ldg((const float4*)Wev + uA * 4 + c4);
            float4 wvB = __ldg((const float4*)Wev + uB * 4 + c4);
            #pragma unroll
            for (int cc = 0; cc < 4; cc++) {
                int c = c4 * 4 + cc;
                unsigned long long wq2 = pack2(f4c(wqA, cc), f4c(wqB, cc));
                unsigned long long wv2 = pack2(f4c(wvA, cc), f4c(wvB, cc));
                #pragma unroll
                for (int j = 0; j < 8; j++) {
                    float f = s_ef[nd][j][c];
                    unsigned long long f2 = pack2(f, f);
                    ffma2(aq[j], f2, wq2);
                    ffma2(av[j], f2, wv2);
                }
            }
        }
        #pragma unroll
        for (int j = 0; j < 8; j++) {
            float2 q2 = unpack2(aq[j]);
            float2 v2 = unpack2(av[j]);
            s_eq[nd][j][uA] = q2.x; s_eq[nd][j][uB] = q2.y;
            s_ev[nd][j][uA] = v2.x; s_ev[nd][j][uB] = v2.y;
        }
        // ek (in = 8 sqk heads)
        unsigned long long ak[8];
        {
            unsigned long long bk2 = pack2(__ldg(&bek[uA]), __ldg(&bek[uB]));
            #pragma unroll
            for (int j = 0; j < 8; j++) ak[j] = bk2;
        }
        #pragma unroll
        for (int c2 = 0; c2 < 2; c2++) {
            float4 wkA = __ldg((const float4*)Wek + uA * 2 + c2);
            float4 wkB = __ldg((const float4*)Wek + uB * 2 + c2);
            #pragma unroll
            for (int cc = 0; cc < 4; cc++) {
                int c = c2 * 4 + cc;
                unsigned long long wk2 = pack2(f4c(wkA, cc), f4c(wkB, cc));
                #pragma unroll
                for (int j = 0; j < 8; j++) {
                    float s = s_sqk[nd][j][c];
                    ffma2(ak[j], pack2(s, s), wk2);
                }
            }
        }
        #pragma unroll
        for (int j = 0; j < 8; j++) {
            float2 k2 = unpack2(ak[j]);
            s_ek[nd][j][uA] = k2.x; s_ek[nd][j][uB] = k2.y;
        }
    }
    __syncwarp();

    // ---- phase 3: edge-edge attention. 2 (q,k) pairs per lane ----
    #pragma unroll
    for (int rep = 0; rep < 2; rep++) {
        int p = lane + 32 * rep;
        int q = p >> 3, k = p & 7;
        const float4* eqp = (const float4*)&s_eq[nd][q][0];
        const float4* ekp = (const float4*)&s_ek[nd][k][0];
        #pragma unroll
        for (int eh = 0; eh < 4; eh++) {
            float s = 0.f;
            #pragma unroll
            for (int c = 0; c < 4; c++) {
                float4 a = eqp[eh * 4 + c];
                float4 b = ekp[eh * 4 + c];
                s += a.x * b.x + a.y * b.y + a.z * b.z + a.w * b.w;
            }
            s *= 0.25f;
            float mx = s;
            mx = fmaxf(mx, __shfl_xor_sync(0xffffffffu, mx, 1));
            mx = fmaxf(mx, __shfl_xor_sync(0xffffffffu, mx, 2));
            mx = fmaxf(mx, __shfl_xor_sync(0xffffffffu, mx, 4));
            float ex = __expf(s - mx);
            float sm = ex;
            sm += __shfl_xor_sync(0xffffffffu, sm, 1);
            sm += __shfl_xor_sync(0xffffffffu, sm, 2);
            sm += __shfl_xor_sync(0xffffffffu, sm, 4);
            s_att[nd][q][eh][k] = __fdividef(ex, sm + 1e-16f);
        }
    }
    __syncwarp();

    // ---- phase 4: eout[q][u] = sum_k att[q][eh(u)][k] * ev[k][u] ----
    #pragma unroll
    for (int rep = 0; rep < 2; rep++) {
        int u = lane + 32 * rep;
        int eh = u >> 4;
        float evr[8];
        #pragma unroll
        for (int k = 0; k < 8; k++) evr[k] = s_ev[nd][k][u];
        #pragma unroll
        for (int q = 0; q < 8; q++) {
            float4 a0 = *(const float4*)&s_att[nd][q][eh][0];
            float4 a1 = *(const float4*)&s_att[nd][q][eh][4];
            float acc = 0.f;
            acc = fmaf(a0.x, evr[0], acc); acc = fmaf(a0.y, evr[1], acc);
            acc = fmaf(a0.z, evr[2], acc); acc = fmaf(a0.w, evr[3], acc);
            acc = fmaf(a1.x, evr[4], acc); acc = fmaf(a1.y, evr[5], acc);
            acc = fmaf(a1.z, evr[6], acc); acc = fmaf(a1.w, evr[7], acc);
            s_eq[nd][q][u] = acc;          // eq reused as eout
        }
    }
    __syncwarp();

    // ---- phase 5: edge_emb[q][h] = eout[q] . Wel[h] + bel[h] ----
    #pragma unroll
    for (int rep = 0; rep < 2; rep++) {
        int p = lane + 32 * rep;
        int q = p >> 3, h = p & 7;
        float acc = __ldg(&bel[h]);
        const float4* ep = (const float4*)&s_eq[nd][q][0];
        const float4* wp = (const float4*)&s_Wel[h][0];
        #pragma unroll
        for (int c = 0; c < 16; c++) {
            float4 e = ep[c], w = wp[c];
            acc += e.x * w.x + e.y * w.y + e.z * w.z + e.w * w.w;
        }
        s_ee[nd][q][h] = acc;
    }
    __syncwarp();

    // ---- phase 6a: node softmax (lanes 0-7) ----
    if (lane < 8) {
        int h = lane;
        float l[8], mx = -1e30f;
        #pragma unroll
        for (int j = 0; j < 8; j++) {
            l[j] = s_ee[nd][j][h] + s_sqk[nd][j][h];
            mx = fmaxf(mx, l[j]);
        }
        float sm = 0.f;
        #pragma unroll
        for (int j = 0; j < 8; j++) { l[j] = __expf(l[j] - mx); sm += l[j]; }
        float inv = __fdividef(1.f, sm + 1e-16f);
        #pragma unroll
        for (int j = 0; j < 8; j++) s_attn[nd][j][h] = l[j] * inv;
    }
    // ---- phase 6b: edge_embeddings output ----
    #pragma unroll
    for (int rep = 0; rep < 2; rep++) {
        int p = lane + 32 * rep;
        int q = p >> 3, d2 = (p & 7) * 2;
        float a0 = __ldg(&bele[d2]), a1 = __ldg(&bele[d2 + 1]);
        #pragma unroll
        for (int h = 0; h < 8; h++) {
            float e = s_ee[nd][q][h];
            a0 = fmaf(e, s_Wele[d2][h], a0);
            a1 = fmaf(e, s_Wele[d2 + 1][h], a1);
        }
        *(float2*)&out_edge[(n * 8 + q) * 16 + d2] = make_float2(a0, a1);
    }
    __syncwarp();

    // ---- phase 7: node aggregation into g_node ----
    #pragma unroll
    for (int i = 0; i < 4; i++) {
        int c4 = lane + 32 * i;            // float4 column index
        int h  = c4 >> 4;
        float4 acc = make_float4(0.f, 0.f, 0.f, 0.f);
        #pragma unroll
        for (int j = 0; j < 8; j++) {
            float w = s_attn[nd][j][h];
            float4 v = __ldg((const float4*)(g_nv + (long)e1r[j] * 512) + c4);
            acc.x = fmaf(w, v.x, acc.x); acc.y = fmaf(w, v.y, acc.y);
            acc.z = fmaf(w, v.z, acc.z); acc.w = fmaf(w, v.w, acc.w);
        }
        ((float4*)(g_node + (long)n * 512))[c4] = acc;
    }
}

// ---------------------------------------------------------------------------
// Kernel 3: node_embeddings = g_node[10000,512] @ Wlin^T[512,64] + blin
// ---------------------------------------------------------------------------
__global__ __launch_bounds__(256) void out_gemm_kernel(
    const float* __restrict__ Wlin, const float* __restrict__ blin,
    float* __restrict__ out)
{
    __shared__ float As[64][68];
    __shared__ float Ws[64][66];
    int r0 = blockIdx.x * 64;
    int t  = threadIdx.x;
    int tx = t & 15, ty = t >> 4;
    unsigned long long acc[4][2] = {};

    for (int k0g = 0; k0g < 512; k0g += 64) {
        __syncthreads();
        #pragma unroll
        for (int i = 0; i < 4; i++) {
            int idx = t + i * 256;
            int row = idx >> 4, k4 = idx & 15;
            float4 v = make_float4(0.f, 0.f, 0.f, 0.f);
            if (r0 + row < NN) v = *(const float4*)&g_node[(long)(r0 + row) * 512 + k0g + k4 * 4];
            *(float4*)&As[row][k4 * 4] = v;
            float4 w = *(const float4*)&Wlin[(long)row * 512 + k0g + k4 * 4];
            Ws[k4*4+0][row] = w.x; Ws[k4*4+1][row] = w.y;
            Ws[k4*4+2][row] = w.z; Ws[k4*4+3][row] = w.w;
        }
        __syncthreads();
        #pragma unroll
        for (int k0 = 0; k0 < 64; k0 += 4) {
            float4 a4[4];
            #pragma unroll
            for (int i = 0; i < 4; i++) a4[i] = *(const float4*)&As[ty * 4 + i][k0];
            #pragma unroll
            for (int kk = 0; kk < 4; kk++) {
                unsigned long long b[2];
                #pragma unroll
                for (int p = 0; p < 2; p++)
                    b[p] = *reinterpret_cast<const unsigned long long*>(&Ws[k0 + kk][tx * 2 + 32 * p]);
                #pragma unroll
                for (int i = 0; i < 4; i++) {
                    float av = ((const float*)&a4[i])[kk];
                    unsigned long long a = pack2(av, av);
                    #pragma unroll
                    for (int p = 0; p < 2; p++)
                        ffma2(acc[i][p], a, b[p]);
                }
            }
        }
    }

    #pragma unroll
    for (int i = 0; i < 4; i++) {
        int row = r0 + ty * 4 + i;
        if (row < NN) {
            #pragma unroll
            for (int p = 0; p < 2; p++) {
                int d = tx * 2 + 32 * p;
                float2 r = unpack2(acc[i][p]);
                *(float2*)&out[(long)row * 64 + d] =
                    make_float2(r.x + blin[d], r.y + blin[d + 1]);
            }
        }
    }
}

// ---------------------------------------------------------------------------
extern "C" void kernel_launch(void* const* d_in, const int* in_sizes, int n_in,
                              void* d_out, int out_size)
{
    const float* x    = (const float*)d_in[0];
    const float* ef   = (const float*)d_in[1];
    const float* Wq   = (const float*)d_in[2];
    const float* bq   = (const float*)d_in[3];
    const float* Wk   = (const float*)d_in[4];
    const float* bk   = (const float*)d_in[5];
    const float* Wv   = (const float*)d_in[6];
    const float* bv   = (const float*)d_in[7];
    const float* Wlin = (const float*)d_in[8];
    const float* blin = (const float*)d_in[9];
    const float* Weq  = (const float*)d_in[10];
    const float* beq  = (const float*)d_in[11];
    const float* Wev  = (const float*)d_in[12];
    const float* bev  = (const float*)d_in[13];
    const float* Wek  = (const float*)d_in[14];
    const float* bek  = (const float*)d_in[15];
    const float* Wel  = (const float*)d_in[16];
    const float* bel  = (const float*)d_in[17];
    const float* Wele = (const float*)d_in[18];
    const float* bele = (const float*)d_in[19];
    const int*   eidx = (const int*)d_in[20];
    float* out = (float*)d_out;

    proj_qkv_kernel<<<dim3(12, 157), 128>>>(x, Wq, bq, Wk, bk, Wv, bv);
    node_edge_kernel<<<NN / 4, 128>>>(ef, eidx, Weq, beq, Wev, bev, Wek, bek,
                                      Wel, bel, Wele, bele, out + NN * 64);
    out_gemm_kernel<<<157, 256>>>(Wlin, blin, out);
}

// round 11
// speedup vs baseline: 1.2788x; 1.0766x over previous
#include <cuda_runtime.h>

#define NN 10000     // nodes
#define KD 8         // out-degree
#define EE 80000     // edges
#define HDIM 512     // H*D

// Scratch (allocation-free rule: __device__ globals)
__device__ float g_nq[NN * HDIM];
__device__ float g_nk[NN * HDIM];
__device__ float g_nv[NN * HDIM];
__device__ float g_node[NN * HDIM];

// ---- packed f32x2 helpers (FFMA2 path: only reachable via PTX) ----
__device__ __forceinline__ unsigned long long pack2(float lo, float hi) {
    unsigned long long r;
    asm("mov.b64 %0, {%1, %2};" : "=l"(r) : "f"(lo), "f"(hi));
    return r;
}
__device__ __forceinline__ void ffma2(unsigned long long& d,
                                      unsigned long long a,
                                      unsigned long long b) {
    asm("fma.rn.f32x2 %0, %1, %2, %0;" : "+l"(d) : "l"(a), "l"(b));
}
__device__ __forceinline__ float2 unpack2(unsigned long long v) {
    float2 f;
    asm("mov.b64 {%0, %1}, %2;" : "=f"(f.x), "=f"(f.y) : "l"(v));
    return f;
}
__device__ __forceinline__ float f4c(const float4& v, int i) {
    return (i == 0) ? v.x : (i == 1) ? v.y : (i == 2) ? v.z : v.w;
}

// ---------------------------------------------------------------------------
// Kernel 1: fused QKV projection (exact R8 version — 50.7us measured).
// 64x128 tile, 8x8 microtile (strided pairs), f32x2 packed FMA.
// ---------------------------------------------------------------------------
__global__ __launch_bounds__(128) void proj_qkv_kernel(
    const float* __restrict__ X,
    const float* __restrict__ Wq, const float* __restrict__ bq,
    const float* __restrict__ Wk, const float* __restrict__ bk,
    const float* __restrict__ Wv, const float* __restrict__ bv)
{
    __shared__ float As[64][68];     // [row][k]
    __shared__ float Bs[64][132];    // [k][col]

    int bx  = blockIdx.x;
    int sel = bx >> 2;
    int c0  = (bx & 3) * 128;
    int r0  = blockIdx.y * 64;
    int t   = threadIdx.x;

    const float* W    = (sel == 0) ? Wq : (sel == 1) ? Wk : Wv;
    const float* bias = (sel == 0) ? bq : (sel == 1) ? bk : bv;
    float*       outp = (sel == 0) ? g_nq : (sel == 1) ? g_nk : g_nv;

    #pragma unroll
    for (int i = 0; i < 8; i++) {
        int idx = t + i * 128;
        int row = idx >> 4, k4 = idx & 15;
        float4 v = make_float4(0.f, 0.f, 0.f, 0.f);
        if (r0 + row < NN) v = *(const float4*)&X[(r0 + row) * 64 + k4 * 4];
        *(float4*)&As[row][k4 * 4] = v;
    }
    #pragma unroll
    for (int i = 0; i < 16; i++) {
        int idx = t + i * 128;
        int c = idx >> 4, k4 = idx & 15;
        float4 w = *(const float4*)&W[(c0 + c) * 64 + k4 * 4];
        Bs[k4*4+0][c] = w.x; Bs[k4*4+1][c] = w.y;
        Bs[k4*4+2][c] = w.z; Bs[k4*4+3][c] = w.w;
    }
    __syncthreads();

    int tx = t & 15, ty = t >> 4;
    unsigned long long acc[8][4] = {};

    #pragma unroll
    for (int k0 = 0; k0 < 64; k0 += 4) {
        float4 a4[8];
        #pragma unroll
        for (int i = 0; i < 8; i++) a4[i] = *(const float4*)&As[ty * 8 + i][k0];
        #pragma unroll
        for (int kk = 0; kk < 4; kk++) {
            unsigned long long b[4];
            #pragma unroll
            for (int p = 0; p < 4; p++)
                b[p] = *reinterpret_cast<const unsigned long long*>(&Bs[k0 + kk][tx * 2 + 32 * p]);
            #pragma unroll
            for (int i = 0; i < 8; i++) {
                float av = ((const float*)&a4[i])[kk];
                unsigned long long a = pack2(av, av);
                #pragma unroll
                for (int p = 0; p < 4; p++)
                    ffma2(acc[i][p], a, b[p]);
            }
        }
    }

    float2 bb[4];
    #pragma unroll
    for (int p = 0; p < 4; p++) {
        int c = c0 + tx * 2 + 32 * p;
        bb[p] = make_float2(bias[c], bias[c + 1]);
    }
    #pragma unroll
    for (int i = 0; i < 8; i++) {
        int row = r0 + ty * 8 + i;
        if (row < NN) {
            #pragma unroll
            for (int p = 0; p < 4; p++) {
                int c = c0 + tx * 2 + 32 * p;
                float2 r = unpack2(acc[i][p]);
                *(float2*)&outp[(long)row * HDIM + c] =
                    make_float2(r.x + bb[p].x, r.y + bb[p].y);
            }
        }
    }
}

// ---------------------------------------------------------------------------
// Kernel 2: warp-per-node fused pipeline (R8 structure). Phase 2 split into
// three sequential stages (eq -> ev -> ek) to cap live registers: target
// <=85 regs so smem (37.2KB) permits 6 blocks/SM (24 warps).
// ---------------------------------------------------------------------------
__global__ __launch_bounds__(128) void node_edge_kernel(
    const float* __restrict__ edge_features,
    const int*   __restrict__ edge_index,
    const float* __restrict__ Weq, const float* __restrict__ beq,
    const float* __restrict__ Wev, const float* __restrict__ bev,
    const float* __restrict__ Wek, const float* __restrict__ bek,
    const float* __restrict__ Wel, const float* __restrict__ bel,
    const float* __restrict__ Wele, const float* __restrict__ bele,
    float* __restrict__ out_edge)
{
    __shared__ __align__(16) float s_Wel[8][68];  // [h][c]
    __shared__ float s_Wele[16][9];               // [de][h]
    // per-node (warp-private) state
    __shared__ __align__(16) float s_ef[4][8][16];
    __shared__ __align__(16) float s_eq[4][8][68];   // eq, reused as eout
    __shared__ __align__(16) float s_ev[4][8][68];
    __shared__ __align__(16) float s_ek[4][8][68];
    __shared__ __align__(16) float s_att[4][8][4][8];
    __shared__ float s_sqk[4][8][8];
    __shared__ float s_ee[4][8][8];
    __shared__ float s_attn[4][8][8];

    int t    = threadIdx.x;
    int nd   = t >> 5;
    int lane = t & 31;
    int n    = blockIdx.x * 4 + nd;

    // ---- stage small weights (block-coop) ----
    for (int i = t; i < 512; i += 128) s_Wel[i >> 6][i & 63] = Wel[i];
    s_Wele[t >> 3][t & 7] = Wele[t];   // t < 128
    __syncthreads();

    // ---- e1 via warp shuffle ----
    int ej = (lane < 8) ? edge_index[EE + n * 8 + lane] : 0;
    int e1r[8];
    #pragma unroll
    for (int j = 0; j < 8; j++) e1r[j] = __shfl_sync(0xffffffffu, ej, j);

    // ---- edge features (128 floats, one float4 per lane) ----
    ((float4*)&s_ef[nd][0][0])[lane] =
        ((const float4*)(edge_features + (long)n * 128))[lane];

    // ---- phase 1: sqk[j][h] head-aligned; 4 lanes per head, 2 shuffles ----
    {
        int hh = lane >> 2, mm = lane & 3;
        const float4* qp = (const float4*)(g_nq + (long)n * 512);
        float4 q4[4];
        #pragma unroll
        for (int i = 0; i < 4; i++) q4[i] = qp[hh * 16 + mm + 4 * i];
        #pragma unroll
        for (int j = 0; j < 8; j++) {
            const float4* kp = (const float4*)(g_nk + (long)e1r[j] * 512);
            float s = 0.f;
            #pragma unroll
            for (int i = 0; i < 4; i++) {
                float4 kv = __ldg(&kp[hh * 16 + mm + 4 * i]);
                s += q4[i].x * kv.x + q4[i].y * kv.y + q4[i].z * kv.z + q4[i].w * kv.w;
            }
            s += __shfl_xor_sync(0xffffffffu, s, 1);
            s += __shfl_xor_sync(0xffffffffu, s, 2);
            if (mm == 0) s_sqk[nd][j][hh] = s * 0.125f;
        }
    }
    __syncwarp();

    // ---- phase 2: eq, then ev, then ek (sequential stages, low reg peak).
    //      lane owns cols uA=lane, uB=lane+32, accumulated as one f32x2 ----
    int uA = lane, uB = lane + 32;
    {   // -- eq --
        unsigned long long aq[8];
        unsigned long long b2 = pack2(__ldg(&beq[uA]), __ldg(&beq[uB]));
        #pragma unroll
        for (int j = 0; j < 8; j++) aq[j] = b2;
        #pragma unroll
        for (int c4 = 0; c4 < 4; c4++) {
            float4 wA = __ldg((const float4*)Weq + uA * 4 + c4);
            float4 wB = __ldg((const float4*)Weq + uB * 4 + c4);
            #pragma unroll
            for (int cc = 0; cc < 4; cc++) {
                int c = c4 * 4 + cc;
                unsigned long long w2 = pack2(f4c(wA, cc), f4c(wB, cc));
                #pragma unroll
                for (int j = 0; j < 8; j++) {
                    float f = s_ef[nd][j][c];
                    ffma2(aq[j], pack2(f, f), w2);
                }
            }
        }
        #pragma unroll
        for (int j = 0; j < 8; j++) {
            float2 q2 = unpack2(aq[j]);
            s_eq[nd][j][uA] = q2.x; s_eq[nd][j][uB] = q2.y;
        }
    }
    {   // -- ev --
        unsigned long long av[8];
        unsigned long long b2 = pack2(__ldg(&bev[uA]), __ldg(&bev[uB]));
        #pragma unroll
        for (int j = 0; j < 8; j++) av[j] = b2;
        #pragma unroll
        for (int c4 = 0; c4 < 4; c4++) {
            float4 wA = __ldg((const float4*)Wev + uA * 4 + c4);
            float4 wB = __ldg((const float4*)Wev + uB * 4 + c4);
            #pragma unroll
            for (int cc = 0; cc < 4; cc++) {
                int c = c4 * 4 + cc;
                unsigned long long w2 = pack2(f4c(wA, cc), f4c(wB, cc));
                #pragma unroll
                for (int j = 0; j < 8; j++) {
                    float f = s_ef[nd][j][c];
                    ffma2(av[j], pack2(f, f), w2);
                }
            }
        }
        #pragma unroll
        for (int j = 0; j < 8; j++) {
            float2 v2 = unpack2(av[j]);
            s_ev[nd][j][uA] = v2.x; s_ev[nd][j][uB] = v2.y;
        }
    }
    {   // -- ek (input = 8 sqk heads) --
        unsigned long long ak[8];
        unsigned long long b2 = pack2(__ldg(&bek[uA]), __ldg(&bek[uB]));
        #pragma unroll
        for (int j = 0; j < 8; j++) ak[j] = b2;
        #pragma unroll
        for (int c2 = 0; c2 < 2; c2++) {
            float4 wA = __ldg((const float4*)Wek + uA * 2 + c2);
            float4 wB = __ldg((const float4*)Wek + uB * 2 + c2);
            #pragma unroll
            for (int cc = 0; cc < 4; cc++) {
                int c = c2 * 4 + cc;
                unsigned long long w2 = pack2(f4c(wA, cc), f4c(wB, cc));
                #pragma unroll
                for (int j = 0; j < 8; j++) {
                    float s = s_sqk[nd][j][c];
                    ffma2(ak[j], pack2(s, s), w2);
                }
            }
        }
        #pragma unroll
        for (int j = 0; j < 8; j++) {
            float2 k2 = unpack2(ak[j]);
            s_ek[nd][j][uA] = k2.x; s_ek[nd][j][uB] = k2.y;
        }
    }
    __syncwarp();

    // ---- phase 3: edge-edge attention. 2 (q,k) pairs per lane ----
    #pragma unroll
    for (int rep = 0; rep < 2; rep++) {
        int p = lane + 32 * rep;
        int q = p >> 3, k = p & 7;
        const float4* eqp = (const float4*)&s_eq[nd][q][0];
        const float4* ekp = (const float4*)&s_ek[nd][k][0];
        #pragma unroll
        for (int eh = 0; eh < 4; eh++) {
            float s = 0.f;
            #pragma unroll
            for (int c = 0; c < 4; c++) {
                float4 a = eqp[eh * 4 + c];
                float4 b = ekp[eh * 4 + c];
                s += a.x * b.x + a.y * b.y + a.z * b.z + a.w * b.w;
            }
            s *= 0.25f;
            float mx = s;
            mx = fmaxf(mx, __shfl_xor_sync(0xffffffffu, mx, 1));
            mx = fmaxf(mx, __shfl_xor_sync(0xffffffffu, mx, 2));
            mx = fmaxf(mx, __shfl_xor_sync(0xffffffffu, mx, 4));
            float ex = __expf(s - mx);
            float sm = ex;
            sm += __shfl_xor_sync(0xffffffffu, sm, 1);
            sm += __shfl_xor_sync(0xffffffffu, sm, 2);
            sm += __shfl_xor_sync(0xffffffffu, sm, 4);
            s_att[nd][q][eh][k] = __fdividef(ex, sm + 1e-16f);
        }
    }
    __syncwarp();

    // ---- phase 4: eout[q][u] = sum_k att[q][eh(u)][k] * ev[k][u] ----
    #pragma unroll
    for (int rep = 0; rep < 2; rep++) {
        int u = lane + 32 * rep;
        int eh = u >> 4;
        float evr[8];
        #pragma unroll
        for (int k = 0; k < 8; k++) evr[k] = s_ev[nd][k][u];
        #pragma unroll
        for (int q = 0; q < 8; q++) {
            float4 a0 = *(const float4*)&s_att[nd][q][eh][0];
            float4 a1 = *(const float4*)&s_att[nd][q][eh][4];
            float acc = 0.f;
            acc = fmaf(a0.x, evr[0], acc); acc = fmaf(a0.y, evr[1], acc);
            acc = fmaf(a0.z, evr[2], acc); acc = fmaf(a0.w, evr[3], acc);
            acc = fmaf(a1.x, evr[4], acc); acc = fmaf(a1.y, evr[5], acc);
            acc = fmaf(a1.z, evr[6], acc); acc = fmaf(a1.w, evr[7], acc);
            s_eq[nd][q][u] = acc;          // eq reused as eout
        }
    }
    __syncwarp();

    // ---- phase 5: edge_emb[q][h] = eout[q] . Wel[h] + bel[h] ----
    #pragma unroll
    for (int rep = 0; rep < 2; rep++) {
        int p = lane + 32 * rep;
        int q = p >> 3, h = p & 7;
        float acc = __ldg(&bel[h]);
        const float4* ep = (const float4*)&s_eq[nd][q][0];
        const float4* wp = (const float4*)&s_Wel[h][0];
        #pragma unroll
        for (int c = 0; c < 16; c++) {
            float4 e = ep[c], w = wp[c];
            acc += e.x * w.x + e.y * w.y + e.z * w.z + e.w * w.w;
        }
        s_ee[nd][q][h] = acc;
    }
    __syncwarp();

    // ---- phase 6a: node softmax (lanes 0-7) ----
    if (lane < 8) {
        int h = lane;
        float l[8], mx = -1e30f;
        #pragma unroll
        for (int j = 0; j < 8; j++) {
            l[j] = s_ee[nd][j][h] + s_sqk[nd][j][h];
            mx = fmaxf(mx, l[j]);
        }
        float sm = 0.f;
        #pragma unroll
        for (int j = 0; j < 8; j++) { l[j] = __expf(l[j] - mx); sm += l[j]; }
        float inv = __fdividef(1.f, sm + 1e-16f);
        #pragma unroll
        for (int j = 0; j < 8; j++) s_attn[nd][j][h] = l[j] * inv;
    }
    // ---- phase 6b: edge_embeddings output ----
    #pragma unroll
    for (int rep = 0; rep < 2; rep++) {
        int p = lane + 32 * rep;
        int q = p >> 3, d2 = (p & 7) * 2;
        float a0 = __ldg(&bele[d2]), a1 = __ldg(&bele[d2 + 1]);
        #pragma unroll
        for (int h = 0; h < 8; h++) {
            float e = s_ee[nd][q][h];
            a0 = fmaf(e, s_Wele[d2][h], a0);
            a1 = fmaf(e, s_Wele[d2 + 1][h], a1);
        }
        *(float2*)&out_edge[(n * 8 + q) * 16 + d2] = make_float2(a0, a1);
    }
    __syncwarp();

    // ---- phase 7: node aggregation into g_node ----
    #pragma unroll
    for (int i = 0; i < 4; i++) {
        int c4 = lane + 32 * i;            // float4 column index
        int h  = c4 >> 4;
        float4 acc = make_float4(0.f, 0.f, 0.f, 0.f);
        #pragma unroll
        for (int j = 0; j < 8; j++) {
            float w = s_attn[nd][j][h];
            float4 v = __ldg((const float4*)(g_nv + (long)e1r[j] * 512) + c4);
            acc.x = fmaf(w, v.x, acc.x); acc.y = fmaf(w, v.y, acc.y);
            acc.z = fmaf(w, v.z, acc.z); acc.w = fmaf(w, v.w, acc.w);
        }
        ((float4*)(g_node + (long)n * 512))[c4] = acc;
    }
}

// ---------------------------------------------------------------------------
// Kernel 3: node_embeddings = g_node[10000,512] @ Wlin^T[512,64] + blin
// ---------------------------------------------------------------------------
__global__ __launch_bounds__(256) void out_gemm_kernel(
    const float* __restrict__ Wlin, const float* __restrict__ blin,
    float* __restrict__ out)
{
    __shared__ float As[64][68];
    __shared__ float Ws[64][66];
    int r0 = blockIdx.x * 64;
    int t  = threadIdx.x;
    int tx = t & 15, ty = t >> 4;
    unsigned long long acc[4][2] = {};

    for (int k0g = 0; k0g < 512; k0g += 64) {
        __syncthreads();
        #pragma unroll
        for (int i = 0; i < 4; i++) {
            int idx = t + i * 256;
            int row = idx >> 4, k4 = idx & 15;
            float4 v = make_float4(0.f, 0.f, 0.f, 0.f);
            if (r0 + row < NN) v = *(const float4*)&g_node[(long)(r0 + row) * 512 + k0g + k4 * 4];
            *(float4*)&As[row][k4 * 4] = v;
            float4 w = *(const float4*)&Wlin[(long)row * 512 + k0g + k4 * 4];
            Ws[k4*4+0][row] = w.x; Ws[k4*4+1][row] = w.y;
            Ws[k4*4+2][row] = w.z; Ws[k4*4+3][row] = w.w;
        }
        __syncthreads();
        #pragma unroll
        for (int k0 = 0; k0 < 64; k0 += 4) {
            float4 a4[4];
            #pragma unroll
            for (int i = 0; i < 4; i++) a4[i] = *(const float4*)&As[ty * 4 + i][k0];
            #pragma unroll
            for (int kk = 0; kk < 4; kk++) {
                unsigned long long b[2];
                #pragma unroll
                for (int p = 0; p < 2; p++)
                    b[p] = *reinterpret_cast<const unsigned long long*>(&Ws[k0 + kk][tx * 2 + 32 * p]);
                #pragma unroll
                for (int i = 0; i < 4; i++) {
                    float av = ((const float*)&a4[i])[kk];
                    unsigned long long a = pack2(av, av);
                    #pragma unroll
                    for (int p = 0; p < 2; p++)
                        ffma2(acc[i][p], a, b[p]);
                }
            }
        }
    }

    #pragma unroll
    for (int i = 0; i < 4; i++) {
        int row = r0 + ty * 4 + i;
        if (row < NN) {
            #pragma unroll
            for (int p = 0; p < 2; p++) {
                int d = tx * 2 + 32 * p;
                float2 r = unpack2(acc[i][p]);
                *(float2*)&out[(long)row * 64 + d] =
                    make_float2(r.x + blin[d], r.y + blin[d + 1]);
            }
        }
    }
}

// ---------------------------------------------------------------------------
extern "C" void kernel_launch(void* const* d_in, const int* in_sizes, int n_in,
                              void* d_out, int out_size)
{
    const float* x    = (const float*)d_in[0];
    const float* ef   = (const float*)d_in[1];
    const float* Wq   = (const float*)d_in[2];
    const float* bq   = (const float*)d_in[3];
    const float* Wk   = (const float*)d_in[4];
    const float* bk   = (const float*)d_in[5];
    const float* Wv   = (const float*)d_in[6];
    const float* bv   = (const float*)d_in[7];
    const float* Wlin = (const float*)d_in[8];
    const float* blin = (const float*)d_in[9];
    const float* Weq  = (const float*)d_in[10];
    const float* beq  = (const float*)d_in[11];
    const float* Wev  = (const float*)d_in[12];
    const float* bev  = (const float*)d_in[13];
    const float* Wek  = (const float*)d_in[14];
    const float* bek  = (const float*)d_in[15];
    const float* Wel  = (const float*)d_in[16];
    const float* bel  = (const float*)d_in[17];
    const float* Wele = (const float*)d_in[18];
    const float* bele = (const float*)d_in[19];
    const int*   eidx = (const int*)d_in[20];
    float* out = (float*)d_out;

    proj_qkv_kernel<<<dim3(12, 157), 128>>>(x, Wq, bq, Wk, bk, Wv, bv);
    node_edge_kernel<<<NN / 4, 128>>>(ef, eidx, Weq, beq, Wev, bev, Wek, bek,
                                      Wel, bel, Wele, bele, out + NN * 64);
    out_gemm_kernel<<<157, 256>>>(Wlin, blin, out);
}